// round 11
// baseline (speedup 1.0000x reference)
#include <cuda_runtime.h>
#include <cuda_fp16.h>
#include <cstdint>
#include <cstddef>

#define DMODEL 1024
#define NHEAD  16
#define DK     64
#define BB     128
#define NN     256
#define MROWS  (BB * NN)   // 32768

typedef unsigned long long ull;

// ============================ helpers ============================
__device__ __forceinline__ uint32_t smem_u32(const void* p) {
    uint32_t a;
    asm("{ .reg .u64 t; cvta.to.shared.u64 t, %1; cvt.u32.u64 %0, t; }" : "=r"(a) : "l"(p));
    return a;
}
__device__ __forceinline__ uint32_t pack2h(float x, float y) {  // low=x, high=y
    uint32_t r; asm("cvt.rn.f16x2.f32 %0, %2, %1;" : "=r"(r) : "f"(x), "f"(y)); return r;
}
__device__ __forceinline__ float fast_exp2(float x) {
    float y; asm("ex2.approx.f32 %0, %1;" : "=f"(y) : "f"(x)); return y;
}
__device__ __forceinline__ void mma16816(float* c, const uint32_t* a, const uint32_t* b) {
    asm volatile("mma.sync.aligned.m16n8k16.row.col.f32.f16.f16.f32 "
        "{%0,%1,%2,%3}, {%4,%5,%6,%7}, {%8,%9}, {%0,%1,%2,%3};"
        : "+f"(c[0]), "+f"(c[1]), "+f"(c[2]), "+f"(c[3])
        : "r"(a[0]), "r"(a[1]), "r"(a[2]), "r"(a[3]), "r"(b[0]), "r"(b[1]));
}
__device__ __forceinline__ void ldsm4(uint32_t* r, uint32_t a) {
    asm volatile("ldmatrix.sync.aligned.m8n8.x4.shared.b16 {%0,%1,%2,%3}, [%4];"
        : "=r"(r[0]), "=r"(r[1]), "=r"(r[2]), "=r"(r[3]) : "r"(a));
}
__device__ __forceinline__ void sts128(uint32_t a, uint32_t x, uint32_t y, uint32_t z, uint32_t w) {
    asm volatile("st.shared.v4.b32 [%0], {%1,%2,%3,%4};" :: "r"(a), "r"(x), "r"(y), "r"(z), "r"(w) : "memory");
}
__device__ __forceinline__ void sts64(uint32_t a, uint32_t x, uint32_t y) {
    asm volatile("st.shared.v2.b32 [%0], {%1,%2};" :: "r"(a), "r"(x), "r"(y) : "memory");
}
__device__ __forceinline__ void sts16(uint32_t a, uint32_t v) {
    asm volatile("st.shared.b16 [%0], %1;" :: "r"(a), "r"(v) : "memory");
}
__device__ __forceinline__ void cpa16(uint32_t dst, const void* src) {
    asm volatile("cp.async.cg.shared.global [%0], [%1], 16;" :: "r"(dst), "l"(src));
}
#define CP_COMMIT() asm volatile("cp.async.commit_group;" ::: "memory")
#define CP_WAIT0()  asm volatile("cp.async.wait_group 0;" ::: "memory")

// ---- scratch ----
__device__ __align__(256) float    g_q[MROWS * DMODEL];
__device__ __align__(256) float    g_k[MROWS * DMODEL];
__device__ __align__(256) float    g_v[MROWS * DMODEL];
__device__ __align__(256) float    g_att[MROWS * DMODEL];
__device__ __align__(256) uint16_t g_wh[4][DMODEL * DMODEL];

// ============================================================================
// prepass: f32 -> fp16 (weights, hi only)
// ============================================================================
__global__ void conv_h(const float4* __restrict__ src, uint2* __restrict__ hi, int n4)
{
    for (int i = blockIdx.x * blockDim.x + threadIdx.x; i < n4;
         i += gridDim.x * blockDim.x) {
        const float4 v = src[i];
        hi[i] = make_uint2(pack2h(v.x, v.y), pack2h(v.z, v.w));
    }
}

// ============================================================================
// HMMA GEMM: C = A(f32 -> fp16 inline) @ W^T(fp16) + bias, 1-term fp16.
// BM=BN=128, BK=64, 8 warps (warp tile 64x32), fp32 accumulators.
// Pitch-144 smem rows (16B-aligned, 144/16=9 odd -> ldsm phases tile all 32
// banks). A: 8xLDG.128 prefetch, early-convert to 16 packed regs. W: cp.async.
// Stage: Ah@0 Wh@18432 (36864 B); 2 stages = 73728 B -> 2 CTA/SM.
// ============================================================================
#define TPH   144
#define TILEB 18432
#define STGB  36864
#define NKS   16

__global__ void __launch_bounds__(256, 2) gemm_mma(
    const float* __restrict__ A, const uint16_t* __restrict__ Wh,
    const float* __restrict__ bias, float* __restrict__ C)
{
    extern __shared__ __align__(128) char dsm[];
    const uint32_t sb = smem_u32(dsm);
    const int t = threadIdx.x, lane = t & 31, wid = t >> 5;
    const int bm = blockIdx.y << 7, bn = blockIdx.x << 7;

    // ---- loader mapping: row = t>>1 (0..127), col half = t&1 (32 cols each) ----
    const int lrow = t >> 1, lh = t & 1;
    const float*    pA  = A  + (size_t)(bm + lrow) * DMODEL + lh * 32;
    const uint16_t* pWh = Wh + (size_t)(bn + lrow) * DMODEL + lh * 32;
    const uint32_t lst = sb + (uint32_t)lrow * TPH + (uint32_t)lh * 64;

    // ---- mma fragment mapping ----
    const int wm = (wid >> 2) * 64, wn = (wid & 3) * 32;
    const int rA = (lane & 7) + ((lane >> 3) & 1) * 8, hA = (lane >> 4) & 1;
    const int rB = (lane & 7) + ((lane >> 4) & 1) * 8, hB = (lane >> 3) & 1;
    uint32_t rowA[4], rowB[2];
#pragma unroll
    for (int mf = 0; mf < 4; mf++) rowA[mf] = (uint32_t)((wm + mf * 16 + rA) * TPH);
#pragma unroll
    for (int p = 0; p < 2; p++)    rowB[p] = (uint32_t)((wn + p * 16 + rB) * TPH);

    float acc[4][4][4];
#pragma unroll
    for (int i = 0; i < 4; i++)
#pragma unroll
        for (int j = 0; j < 4; j++)
#pragma unroll
            for (int e = 0; e < 4; e++) acc[i][j][e] = 0.f;

    uint32_t ah[16];

    auto loadA = [&](int k0) {
#pragma unroll
        for (int i = 0; i < 8; i++) {
            const float4 v = *(const float4*)(pA + k0 + i * 4);
            ah[2 * i]     = pack2h(v.x, v.y);
            ah[2 * i + 1] = pack2h(v.z, v.w);
        }
    };
    auto storeA = [&](uint32_t d) {
#pragma unroll
        for (int j = 0; j < 4; j++)
            sts128(d + j * 16, ah[4 * j], ah[4 * j + 1], ah[4 * j + 2], ah[4 * j + 3]);
    };
    auto issueW = [&](uint32_t d, int k0) {
#pragma unroll
        for (int j = 0; j < 4; j++)
            cpa16(d + TILEB + j * 16, pWh + k0 + j * 8);
        CP_COMMIT();
    };

    // ---- prologue: stage 0 ----
    issueW(lst, 0);
    loadA(0);
    storeA(lst);
    CP_WAIT0();
    __syncthreads();

    for (int s = 0; s < NKS; s++) {
        const uint32_t dn = lst + (uint32_t)((s + 1) & 1) * STGB;
        if (s + 1 < NKS) {
            const int k0 = (s + 1) * 64;
            issueW(dn, k0);
            loadA(k0);
        }

        const uint32_t base = sb + (uint32_t)(s & 1) * STGB;
#pragma unroll
        for (int ks = 0; ks < 4; ks++) {
            const uint32_t offA = (uint32_t)(ks * 32 + hA * 16);
            const uint32_t offB = (uint32_t)(ks * 32 + hB * 16);
            uint32_t af[4][4], wf[2][4];
#pragma unroll
            for (int mf = 0; mf < 4; mf++) ldsm4(af[mf], base + rowA[mf] + offA);
#pragma unroll
            for (int p = 0; p < 2; p++)    ldsm4(wf[p], base + TILEB + rowB[p] + offB);
#pragma unroll
            for (int mf = 0; mf < 4; mf++)
#pragma unroll
                for (int nf = 0; nf < 4; nf++)
                    mma16816(acc[mf][nf], af[mf], &wf[nf >> 1][(nf & 1) * 2]);
        }

        if (s + 1 < NKS) storeA(dn);
        CP_WAIT0();
        __syncthreads();
    }

    // ---- epilogue: acc + bias -> C ----
    const int g = lane >> 2, tg = lane & 3;
#pragma unroll
    for (int mf = 0; mf < 4; mf++) {
        const int row0 = bm + wm + mf * 16 + g;
#pragma unroll
        for (int nf = 0; nf < 4; nf++) {
            const int col = bn + wn + nf * 8 + tg * 2;
            const float bx = bias[col], by = bias[col + 1];
            float2 o0, o1;
            o0.x = acc[mf][nf][0] + bx; o0.y = acc[mf][nf][1] + by;
            o1.x = acc[mf][nf][2] + bx; o1.y = acc[mf][nf][3] + by;
            *(float2*)&C[(size_t)row0 * DMODEL + col]       = o0;
            *(float2*)&C[(size_t)(row0 + 8) * DMODEL + col] = o1;
        }
    }
}

// ============================================================================
// HMMA intersample attention (unchanged from R9): one block per (h, n).
// ============================================================================
#define PQ   72
#define PVT  136
#define OFF_QH 0
#define OFF_QL 18432
#define OFF_KH 36864
#define OFF_KL 55296
#define OFF_VH 73728
#define OFF_VL 91136
#define ATT_SMEM 108544

__global__ void __launch_bounds__(256, 2) attn_mma(
    const float* __restrict__ gq, const float* __restrict__ gk,
    const float* __restrict__ gv, float* __restrict__ go)
{
    extern __shared__ __align__(128) uint16_t sm2[];
    const uint32_t sb = smem_u32(sm2);
    const int t = threadIdx.x, lane = t & 31, wid = t >> 5;
    const int n = blockIdx.x, h = blockIdx.y;
    const int    base = n * DMODEL + h * DK;
    const size_t rstr = (size_t)NN * DMODEL;

    {
        const int row = t >> 1, lh = t & 1;
        const float* qp = gq + base + (size_t)row * rstr + lh * 32;
        const float* kp = gk + base + (size_t)row * rstr + lh * 32;
        const float* vp = gv + base + (size_t)row * rstr + lh * 32;
        const uint32_t qdst = sb + (uint32_t)(row * PQ + lh * 32) * 2;
#pragma unroll
        for (int i = 0; i < 8; i++) {
            const float4 qv = *(const float4*)(qp + i * 4);
            const float4 kv = *(const float4*)(kp + i * 4);
            const float4 vv = *(const float4*)(vp + i * 4);
            uint32_t h0 = pack2h(qv.x, qv.y), h1 = pack2h(qv.z, qv.w);
            __half2 a0 = *(const __half2*)&h0, a1 = *(const __half2*)&h1;
            uint32_t l0 = pack2h(qv.x - __low2float(a0), qv.y - __high2float(a0));
            uint32_t l1 = pack2h(qv.z - __low2float(a1), qv.w - __high2float(a1));
            sts64(qdst + OFF_QH + i * 8, h0, h1);
            sts64(qdst + OFF_QL + i * 8, l0, l1);
            h0 = pack2h(kv.x, kv.y); h1 = pack2h(kv.z, kv.w);
            a0 = *(const __half2*)&h0; a1 = *(const __half2*)&h1;
            l0 = pack2h(kv.x - __low2float(a0), kv.y - __high2float(a0));
            l1 = pack2h(kv.z - __low2float(a1), kv.w - __high2float(a1));
            sts64(qdst + OFF_KH + i * 8, h0, h1);
            sts64(qdst + OFF_KL + i * 8, l0, l1);
            const float vs[4] = { vv.x, vv.y, vv.z, vv.w };
#pragma unroll
            for (int j = 0; j < 4; j++) {
                const int d = lh * 32 + i * 4 + j;
                const __half vh = __float2half_rn(vs[j]);
                const __half vl = __float2half_rn(vs[j] - __half2float(vh));
                const uint32_t ta = sb + (uint32_t)(d * PVT + row) * 2;
                sts16(ta + OFF_VH, (uint32_t)__half_as_ushort(vh));
                sts16(ta + OFF_VL, (uint32_t)__half_as_ushort(vl));
            }
        }
    }
    __syncthreads();

    const int wm = wid * 16;
    const int rA = (lane & 7) + ((lane >> 3) & 1) * 8, hA = (lane >> 4) & 1;
    const int rB = (lane & 7) + ((lane >> 4) & 1) * 8, hB = (lane >> 3) & 1;
    const uint32_t rowAq = (uint32_t)((wm + rA) * PQ) * 2;

    float s[16][4];
#pragma unroll
    for (int i = 0; i < 16; i++)
#pragma unroll
        for (int e = 0; e < 4; e++) s[i][e] = 0.f;

#pragma unroll
    for (int ks = 0; ks < 4; ks++) {
        const uint32_t offA = (uint32_t)((ks * 2 + hA) * 16);
        const uint32_t offB = (uint32_t)((ks * 2 + hB) * 16);
        uint32_t aqh[4], aql[4], kf[8][4];
        ldsm4(aqh, sb + OFF_QH + rowAq + offA);
        ldsm4(aql, sb + OFF_QL + rowAq + offA);
#pragma unroll
        for (int p = 0; p < 8; p++)
            ldsm4(kf[p], sb + OFF_KH + (uint32_t)((p * 16 + rB) * PQ) * 2 + offB);
#pragma unroll
        for (int nf = 0; nf < 16; nf++) mma16816(s[nf], aqh, &kf[nf >> 1][(nf & 1) * 2]);
#pragma unroll
        for (int nf = 0; nf < 16; nf++) mma16816(s[nf], aql, &kf[nf >> 1][(nf & 1) * 2]);
#pragma unroll
        for (int p = 0; p < 8; p++)
            ldsm4(kf[p], sb + OFF_KL + (uint32_t)((p * 16 + rB) * PQ) * 2 + offB);
#pragma unroll
        for (int nf = 0; nf < 16; nf++) mma16816(s[nf], aqh, &kf[nf >> 1][(nf & 1) * 2]);
    }

    float mx0 = -1e30f, mx1 = -1e30f;
#pragma unroll
    for (int nf = 0; nf < 16; nf++) {
        mx0 = fmaxf(mx0, fmaxf(s[nf][0], s[nf][1]));
        mx1 = fmaxf(mx1, fmaxf(s[nf][2], s[nf][3]));
    }
    mx0 = fmaxf(mx0, __shfl_xor_sync(0xffffffff, mx0, 1));
    mx0 = fmaxf(mx0, __shfl_xor_sync(0xffffffff, mx0, 2));
    mx1 = fmaxf(mx1, __shfl_xor_sync(0xffffffff, mx1, 1));
    mx1 = fmaxf(mx1, __shfl_xor_sync(0xffffffff, mx1, 2));
    const float cf = 0.125f * 1.4426950408889634f;
    float sum0 = 0.f, sum1 = 0.f;
#pragma unroll
    for (int nf = 0; nf < 16; nf++) {
        s[nf][0] = fast_exp2((s[nf][0] - mx0) * cf);
        s[nf][1] = fast_exp2((s[nf][1] - mx0) * cf);
        s[nf][2] = fast_exp2((s[nf][2] - mx1) * cf);
        s[nf][3] = fast_exp2((s[nf][3] - mx1) * cf);
        sum0 += s[nf][0] + s[nf][1];
        sum1 += s[nf][2] + s[nf][3];
    }
    sum0 += __shfl_xor_sync(0xffffffff, sum0, 1);
    sum0 += __shfl_xor_sync(0xffffffff, sum0, 2);
    sum1 += __shfl_xor_sync(0xffffffff, sum1, 1);
    sum1 += __shfl_xor_sync(0xffffffff, sum1, 2);
    const float inv0 = 1.0f / sum0, inv1 = 1.0f / sum1;

    float o[8][4];
#pragma unroll
    for (int i = 0; i < 8; i++)
#pragma unroll
        for (int e = 0; e < 4; e++) o[i][e] = 0.f;

#pragma unroll
    for (int ks = 0; ks < 8; ks++) {
        uint32_t ph[4], pl[4];
        {
            const float* e0 = s[2 * ks];
            const float* e1 = s[2 * ks + 1];
            ph[0] = pack2h(e0[0], e0[1]); ph[1] = pack2h(e0[2], e0[3]);
            ph[2] = pack2h(e1[0], e1[1]); ph[3] = pack2h(e1[2], e1[3]);
            const __half2 q0 = *(const __half2*)&ph[0], q1 = *(const __half2*)&ph[1];
            const __half2 q2 = *(const __half2*)&ph[2], q3 = *(const __half2*)&ph[3];
            pl[0] = pack2h(e0[0] - __low2float(q0), e0[1] - __high2float(q0));
            pl[1] = pack2h(e0[2] - __low2float(q1), e0[3] - __high2float(q1));
            pl[2] = pack2h(e1[0] - __low2float(q2), e1[1] - __high2float(q2));
            pl[3] = pack2h(e1[2] - __low2float(q3), e1[3] - __high2float(q3));
        }
        const uint32_t offB = (uint32_t)((ks * 2 + hB) * 16);
        uint32_t vf[4][4];
#pragma unroll
        for (int p = 0; p < 4; p++)
            ldsm4(vf[p], sb + OFF_VH + (uint32_t)((p * 16 + rB) * PVT) * 2 + offB);
#pragma unroll
        for (int nf = 0; nf < 8; nf++) mma16816(o[nf], ph, &vf[nf >> 1][(nf & 1) * 2]);
#pragma unroll
        for (int nf = 0; nf < 8; nf++) mma16816(o[nf], pl, &vf[nf >> 1][(nf & 1) * 2]);
#pragma unroll
        for (int p = 0; p < 4; p++)
            ldsm4(vf[p], sb + OFF_VL + (uint32_t)((p * 16 + rB) * PVT) * 2 + offB);
#pragma unroll
        for (int nf = 0; nf < 8; nf++) mma16816(o[nf], ph, &vf[nf >> 1][(nf & 1) * 2]);
    }

    const int g = lane >> 2, tg = lane & 3;
    const int row0 = wm + g, row1 = row0 + 8;
#pragma unroll
    for (int nf = 0; nf < 8; nf++) {
        const int d = nf * 8 + tg * 2;
        float2 v0, v1;
        v0.x = o[nf][0] * inv0; v0.y = o[nf][1] * inv0;
        v1.x = o[nf][2] * inv1; v1.y = o[nf][3] * inv1;
        *(float2*)&go[base + (size_t)row0 * rstr + d] = v0;
        *(float2*)&go[base + (size_t)row1 * rstr + d] = v1;
    }
}

// ============================================================================
// kernel_launch
// ============================================================================
extern "C" void kernel_launch(void* const* d_in, const int* in_sizes, int n_in,
                              void* d_out, int out_size)
{
    const float* query = (const float*)d_in[0];
    const float* key   = (const float*)d_in[1];
    const float* value = (const float*)d_in[2];
    const float* Wq    = (const float*)d_in[3];
    const float* bq    = (const float*)d_in[4];
    const float* Wk    = (const float*)d_in[5];
    const float* bk    = (const float*)d_in[6];
    const float* Wv    = (const float*)d_in[7];
    const float* bv    = (const float*)d_in[8];
    const float* Wo    = (const float*)d_in[9];
    const float* bo    = (const float*)d_in[10];
    float* out = (float*)d_out;

    float *pq, *pk, *pv, *pa;
    uint16_t *wh;
    cudaGetSymbolAddress((void**)&pq, g_q);
    cudaGetSymbolAddress((void**)&pk, g_k);
    cudaGetSymbolAddress((void**)&pv, g_v);
    cudaGetSymbolAddress((void**)&pa, g_att);
    cudaGetSymbolAddress((void**)&wh, g_wh);

    const int gsmem = 2 * STGB;   // 73728 B
    static int s_attr = 0;
    if (!s_attr) {
        cudaFuncSetAttribute(gemm_mma, cudaFuncAttributeMaxDynamicSharedMemorySize, gsmem);
        cudaFuncSetAttribute(attn_mma, cudaFuncAttributeMaxDynamicSharedMemorySize, ATT_SMEM);
        s_attr = 1;
    }

    const int n4w = DMODEL * DMODEL / 4;
    conv_h<<<1024, 256>>>((const float4*)Wq, (uint2*)(wh + 0 * DMODEL * DMODEL), n4w);
    conv_h<<<1024, 256>>>((const float4*)Wk, (uint2*)(wh + 1 * DMODEL * DMODEL), n4w);
    conv_h<<<1024, 256>>>((const float4*)Wv, (uint2*)(wh + 2 * DMODEL * DMODEL), n4w);
    conv_h<<<1024, 256>>>((const float4*)Wo, (uint2*)(wh + 3 * DMODEL * DMODEL), n4w);

    const dim3 ggrid(DMODEL / 128, MROWS / 128);   // (8, 256)
    gemm_mma<<<ggrid, 256, gsmem>>>(query, wh + 0 * DMODEL * DMODEL, bq, pq);
    gemm_mma<<<ggrid, 256, gsmem>>>(key,   wh + 1 * DMODEL * DMODEL, bk, pk);
    gemm_mma<<<ggrid, 256, gsmem>>>(value, wh + 2 * DMODEL * DMODEL, bv, pv);

    attn_mma<<<dim3(NN, NHEAD), 256, ATT_SMEM>>>(pq, pk, pv, pa);

    gemm_mma<<<ggrid, 256, gsmem>>>(pa, wh + 3 * DMODEL * DMODEL, bo, out);
}

// round 15
// speedup vs baseline: 1.3134x; 1.3134x over previous
#include <cuda_runtime.h>
#include <cuda_fp16.h>
#include <cstdint>
#include <cstddef>

#define DMODEL 1024
#define NHEAD  16
#define DK     64
#define BB     128
#define NN     256
#define MROWS  (BB * NN)   // 32768

typedef unsigned long long ull;

// ============================ helpers ============================
__device__ __forceinline__ uint32_t smem_u32(const void* p) {
    uint32_t a;
    asm("{ .reg .u64 t; cvta.to.shared.u64 t, %1; cvt.u32.u64 %0, t; }" : "=r"(a) : "l"(p));
    return a;
}
__device__ __forceinline__ uint32_t pack2h(float x, float y) {  // low=x, high=y
    uint32_t r; asm("cvt.rn.f16x2.f32 %0, %2, %1;" : "=r"(r) : "f"(x), "f"(y)); return r;
}
__device__ __forceinline__ float fast_exp2(float x) {
    float y; asm("ex2.approx.f32 %0, %1;" : "=f"(y) : "f"(x)); return y;
}
__device__ __forceinline__ void mma16816(float* c, const uint32_t* a, const uint32_t* b) {
    asm volatile("mma.sync.aligned.m16n8k16.row.col.f32.f16.f16.f32 "
        "{%0,%1,%2,%3}, {%4,%5,%6,%7}, {%8,%9}, {%0,%1,%2,%3};"
        : "+f"(c[0]), "+f"(c[1]), "+f"(c[2]), "+f"(c[3])
        : "r"(a[0]), "r"(a[1]), "r"(a[2]), "r"(a[3]), "r"(b[0]), "r"(b[1]));
}
__device__ __forceinline__ void ldsm4(uint32_t* r, uint32_t a) {
    asm volatile("ldmatrix.sync.aligned.m8n8.x4.shared.b16 {%0,%1,%2,%3}, [%4];"
        : "=r"(r[0]), "=r"(r[1]), "=r"(r[2]), "=r"(r[3]) : "r"(a));
}
__device__ __forceinline__ void sts128(uint32_t a, uint32_t x, uint32_t y, uint32_t z, uint32_t w) {
    asm volatile("st.shared.v4.b32 [%0], {%1,%2,%3,%4};" :: "r"(a), "r"(x), "r"(y), "r"(z), "r"(w) : "memory");
}
__device__ __forceinline__ void sts64(uint32_t a, uint32_t x, uint32_t y) {
    asm volatile("st.shared.v2.b32 [%0], {%1,%2};" :: "r"(a), "r"(x), "r"(y) : "memory");
}
__device__ __forceinline__ void sts16(uint32_t a, uint32_t v) {
    asm volatile("st.shared.b16 [%0], %1;" :: "r"(a), "r"(v) : "memory");
}
__device__ __forceinline__ void cpa16(uint32_t dst, const void* src) {
    asm volatile("cp.async.cg.shared.global [%0], [%1], 16;" :: "r"(dst), "l"(src));
}
#define CP_COMMIT() asm volatile("cp.async.commit_group;" ::: "memory")
#define CP_WAIT0()  asm volatile("cp.async.wait_group 0;" ::: "memory")

// ---- scratch ----
__device__ __align__(256) float    g_q[MROWS * DMODEL];
__device__ __align__(256) float    g_k[MROWS * DMODEL];
__device__ __align__(256) float    g_v[MROWS * DMODEL];
__device__ __align__(256) float    g_att[MROWS * DMODEL];
__device__ __align__(256) uint16_t g_wh[4][DMODEL * DMODEL];

// ============================================================================
// prepass: f32 -> fp16 (weights, hi only)
// ============================================================================
__global__ void conv_h(const float4* __restrict__ src, uint2* __restrict__ hi, int n4)
{
    for (int i = blockIdx.x * blockDim.x + threadIdx.x; i < n4;
         i += gridDim.x * blockDim.x) {
        const float4 v = src[i];
        hi[i] = make_uint2(pack2h(v.x, v.y), pack2h(v.z, v.w));
    }
}

// ============================================================================
// HMMA GEMM (exact R9 config — proven 310us/GEMM):
// C = A(f32 -> fp16 inline) @ W^T(fp16) + bias, 1-term fp16.
// BM=BN=128, BK=32, 8 warps, pitch-80, double-buffered, 2 CTA/SM.
// ============================================================================
#define TP   80
#define TSZ  10240
#define STG  20480
#define NKS  32

__global__ void __launch_bounds__(256, 2) gemm_mma(
    const float* __restrict__ A, const uint16_t* __restrict__ Wh,
    const float* __restrict__ bias, float* __restrict__ C)
{
    extern __shared__ __align__(128) char dsm[];
    const uint32_t sb = smem_u32(dsm);
    const int t = threadIdx.x, lane = t & 31, wid = t >> 5;
    const int bm = blockIdx.y << 7, bn = blockIdx.x << 7;

    const int lrow = t >> 1, lh = t & 1;
    const float*    pA  = A  + (size_t)(bm + lrow) * DMODEL + lh * 16;
    const uint16_t* pWh = Wh + (size_t)(bn + lrow) * DMODEL + lh * 16;
    const uint32_t lst = sb + (uint32_t)lrow * TP + (uint32_t)lh * 32;

    const int wm = (wid >> 2) * 64, wn = (wid & 3) * 32;
    const int rA = (lane & 7) + ((lane >> 3) & 1) * 8, hA = (lane >> 4) & 1;
    const int rB = (lane & 7) + ((lane >> 4) & 1) * 8, hB = (lane >> 3) & 1;
    uint32_t rowA[4], rowB[2];
#pragma unroll
    for (int mf = 0; mf < 4; mf++) rowA[mf] = (uint32_t)((wm + mf * 16 + rA) * TP);
#pragma unroll
    for (int p = 0; p < 2; p++)    rowB[p] = (uint32_t)((wn + p * 16 + rB) * TP);

    float acc[4][4][4];
#pragma unroll
    for (int i = 0; i < 4; i++)
#pragma unroll
        for (int j = 0; j < 4; j++)
#pragma unroll
            for (int e = 0; e < 4; e++) acc[i][j][e] = 0.f;

    float4 va[4];

    auto storeA = [&](uint32_t d) {
        uint32_t hh[4], h2[4];
#pragma unroll
        for (int i = 0; i < 4; i++) {
            hh[i] = pack2h(va[i].x, va[i].y);
            h2[i] = pack2h(va[i].z, va[i].w);
        }
        sts128(d,      hh[0], h2[0], hh[1], h2[1]);
        sts128(d + 16, hh[2], h2[2], hh[3], h2[3]);
    };
    auto issueW = [&](uint32_t d, int k0) {
        cpa16(d + TSZ,      pWh + k0);
        cpa16(d + TSZ + 16, pWh + k0 + 8);
        CP_COMMIT();
    };

    issueW(lst, 0);
#pragma unroll
    for (int i = 0; i < 4; i++) va[i] = *(const float4*)(pA + i * 4);
    storeA(lst);
    CP_WAIT0();
    __syncthreads();

    for (int s = 0; s < NKS; s++) {
        const uint32_t dn = lst + (uint32_t)((s + 1) & 1) * STG;
        if (s + 1 < NKS) {
            const int k0 = (s + 1) * 32;
            issueW(dn, k0);
#pragma unroll
            for (int i = 0; i < 4; i++) va[i] = *(const float4*)(pA + k0 + i * 4);
        }

        const uint32_t base = sb + (uint32_t)(s & 1) * STG;
#pragma unroll
        for (int ks = 0; ks < 2; ks++) {
            const uint32_t offA = (uint32_t)(ks * 32 + hA * 16);
            const uint32_t offB = (uint32_t)(ks * 32 + hB * 16);
            uint32_t af[4][4], wf[2][4];
#pragma unroll
            for (int mf = 0; mf < 4; mf++) ldsm4(af[mf], base + rowA[mf] + offA);
#pragma unroll
            for (int p = 0; p < 2; p++)    ldsm4(wf[p], base + TSZ + rowB[p] + offB);
#pragma unroll
            for (int mf = 0; mf < 4; mf++)
#pragma unroll
                for (int nf = 0; nf < 4; nf++)
                    mma16816(acc[mf][nf], af[mf], &wf[nf >> 1][(nf & 1) * 2]);
        }

        if (s + 1 < NKS) storeA(dn);
        CP_WAIT0();
        __syncthreads();
    }

    const int g = lane >> 2, tg = lane & 3;
#pragma unroll
    for (int mf = 0; mf < 4; mf++) {
        const int row0 = bm + wm + mf * 16 + g;
#pragma unroll
        for (int nf = 0; nf < 4; nf++) {
            const int col = bn + wn + nf * 8 + tg * 2;
            const float bx = bias[col], by = bias[col + 1];
            float2 o0, o1;
            o0.x = acc[mf][nf][0] + bx; o0.y = acc[mf][nf][1] + by;
            o1.x = acc[mf][nf][2] + bx; o1.y = acc[mf][nf][3] + by;
            *(float2*)&C[(size_t)row0 * DMODEL + col]       = o0;
            *(float2*)&C[(size_t)(row0 + 8) * DMODEL + col] = o1;
        }
    }
}

// ============================================================================
// HMMA intersample attention: one block per (h, n).
// S = Qh*Kh + Ql*Kh (2-term; K-residual dropped, ~1e-4 component).
// O = Ph*Vh + Pl*Vh (2-term; V-residual dropped, ~1e-4 component).
// smem: Qh Ql Kh [128][72]h + VhT [64][136]h = 72704 B -> 2 CTA/SM.
// ============================================================================
#define PQ   72
#define PVT  136
#define OFF_QH 0
#define OFF_QL 18432
#define OFF_KH 36864
#define OFF_VH 55296
#define ATT_SMEM 72704

__global__ void __launch_bounds__(256, 2) attn_mma(
    const float* __restrict__ gq, const float* __restrict__ gk,
    const float* __restrict__ gv, float* __restrict__ go)
{
    extern __shared__ __align__(128) uint16_t sm2[];
    const uint32_t sb = smem_u32(sm2);
    const int t = threadIdx.x, lane = t & 31, wid = t >> 5;
    const int n = blockIdx.x, h = blockIdx.y;
    const int    base = n * DMODEL + h * DK;
    const size_t rstr = (size_t)NN * DMODEL;

    // ---- load + convert: thread -> row (t>>1), d-half (t&1)*32 ----
    {
        const int row = t >> 1, lh = t & 1;
        const float* qp = gq + base + (size_t)row * rstr + lh * 32;
        const float* kp = gk + base + (size_t)row * rstr + lh * 32;
        const float* vp = gv + base + (size_t)row * rstr + lh * 32;
        const uint32_t qdst = sb + (uint32_t)(row * PQ + lh * 32) * 2;
#pragma unroll
        for (int i = 0; i < 8; i++) {
            const float4 qv = *(const float4*)(qp + i * 4);
            const float4 kv = *(const float4*)(kp + i * 4);
            const float4 vv = *(const float4*)(vp + i * 4);
            // Q hi + lo
            uint32_t h0 = pack2h(qv.x, qv.y), h1 = pack2h(qv.z, qv.w);
            __half2 a0 = *(const __half2*)&h0, a1 = *(const __half2*)&h1;
            uint32_t l0 = pack2h(qv.x - __low2float(a0), qv.y - __high2float(a0));
            uint32_t l1 = pack2h(qv.z - __low2float(a1), qv.w - __high2float(a1));
            sts64(qdst + OFF_QH + i * 8, h0, h1);
            sts64(qdst + OFF_QL + i * 8, l0, l1);
            // K hi only
            h0 = pack2h(kv.x, kv.y); h1 = pack2h(kv.z, kv.w);
            sts64(qdst + OFF_KH + i * 8, h0, h1);
            // V hi only, transposed [d][c]
            const float vs[4] = { vv.x, vv.y, vv.z, vv.w };
#pragma unroll
            for (int j = 0; j < 4; j++) {
                const int d = lh * 32 + i * 4 + j;
                const __half vh = __float2half_rn(vs[j]);
                const uint32_t ta = sb + (uint32_t)(d * PVT + row) * 2;
                sts16(ta + OFF_VH, (uint32_t)__half_as_ushort(vh));
            }
        }
    }
    __syncthreads();

    // ---- fragment mappings ----
    const int wm = wid * 16;
    const int rA = (lane & 7) + ((lane >> 3) & 1) * 8, hA = (lane >> 4) & 1;
    const int rB = (lane & 7) + ((lane >> 4) & 1) * 8, hB = (lane >> 3) & 1;
    const uint32_t rowAq = (uint32_t)((wm + rA) * PQ) * 2;

    float s[16][4];
#pragma unroll
    for (int i = 0; i < 16; i++)
#pragma unroll
        for (int e = 0; e < 4; e++) s[i][e] = 0.f;

    // ---- S = Q K^T (2-term) ----
#pragma unroll
    for (int ks = 0; ks < 4; ks++) {
        const uint32_t offA = (uint32_t)((ks * 2 + hA) * 16);
        const uint32_t offB = (uint32_t)((ks * 2 + hB) * 16);
        uint32_t aqh[4], aql[4], kf[8][4];
        ldsm4(aqh, sb + OFF_QH + rowAq + offA);
        ldsm4(aql, sb + OFF_QL + rowAq + offA);
#pragma unroll
        for (int p = 0; p < 8; p++)
            ldsm4(kf[p], sb + OFF_KH + (uint32_t)((p * 16 + rB) * PQ) * 2 + offB);
#pragma unroll
        for (int nf = 0; nf < 16; nf++) mma16816(s[nf], aqh, &kf[nf >> 1][(nf & 1) * 2]);
#pragma unroll
        for (int nf = 0; nf < 16; nf++) mma16816(s[nf], aql, &kf[nf >> 1][(nf & 1) * 2]);
    }

    // ---- softmax in registers ----
    float mx0 = -1e30f, mx1 = -1e30f;
#pragma unroll
    for (int nf = 0; nf < 16; nf++) {
        mx0 = fmaxf(mx0, fmaxf(s[nf][0], s[nf][1]));
        mx1 = fmaxf(mx1, fmaxf(s[nf][2], s[nf][3]));
    }
    mx0 = fmaxf(mx0, __shfl_xor_sync(0xffffffff, mx0, 1));
    mx0 = fmaxf(mx0, __shfl_xor_sync(0xffffffff, mx0, 2));
    mx1 = fmaxf(mx1, __shfl_xor_sync(0xffffffff, mx1, 1));
    mx1 = fmaxf(mx1, __shfl_xor_sync(0xffffffff, mx1, 2));
    const float cf = 0.125f * 1.4426950408889634f;
    float sum0 = 0.f, sum1 = 0.f;
#pragma unroll
    for (int nf = 0; nf < 16; nf++) {
        s[nf][0] = fast_exp2((s[nf][0] - mx0) * cf);
        s[nf][1] = fast_exp2((s[nf][1] - mx0) * cf);
        s[nf][2] = fast_exp2((s[nf][2] - mx1) * cf);
        s[nf][3] = fast_exp2((s[nf][3] - mx1) * cf);
        sum0 += s[nf][0] + s[nf][1];
        sum1 += s[nf][2] + s[nf][3];
    }
    sum0 += __shfl_xor_sync(0xffffffff, sum0, 1);
    sum0 += __shfl_xor_sync(0xffffffff, sum0, 2);
    sum1 += __shfl_xor_sync(0xffffffff, sum1, 1);
    sum1 += __shfl_xor_sync(0xffffffff, sum1, 2);
    const float inv0 = 1.0f / sum0, inv1 = 1.0f / sum1;

    // ---- O = P V (2-term), P from registers ----
    float o[8][4];
#pragma unroll
    for (int i = 0; i < 8; i++)
#pragma unroll
        for (int e = 0; e < 4; e++) o[i][e] = 0.f;

#pragma unroll
    for (int ks = 0; ks < 8; ks++) {
        uint32_t ph[4], pl[4];
        {
            const float* e0 = s[2 * ks];
            const float* e1 = s[2 * ks + 1];
            ph[0] = pack2h(e0[0], e0[1]); ph[1] = pack2h(e0[2], e0[3]);
            ph[2] = pack2h(e1[0], e1[1]); ph[3] = pack2h(e1[2], e1[3]);
            const __half2 q0 = *(const __half2*)&ph[0], q1 = *(const __half2*)&ph[1];
            const __half2 q2 = *(const __half2*)&ph[2], q3 = *(const __half2*)&ph[3];
            pl[0] = pack2h(e0[0] - __low2float(q0), e0[1] - __high2float(q0));
            pl[1] = pack2h(e0[2] - __low2float(q1), e0[3] - __high2float(q1));
            pl[2] = pack2h(e1[0] - __low2float(q2), e1[1] - __high2float(q2));
            pl[3] = pack2h(e1[2] - __low2float(q3), e1[3] - __high2float(q3));
        }
        const uint32_t offB = (uint32_t)((ks * 2 + hB) * 16);
        uint32_t vf[4][4];
#pragma unroll
        for (int p = 0; p < 4; p++)
            ldsm4(vf[p], sb + OFF_VH + (uint32_t)((p * 16 + rB) * PVT) * 2 + offB);
#pragma unroll
        for (int nf = 0; nf < 8; nf++) mma16816(o[nf], ph, &vf[nf >> 1][(nf & 1) * 2]);
#pragma unroll
        for (int nf = 0; nf < 8; nf++) mma16816(o[nf], pl, &vf[nf >> 1][(nf & 1) * 2]);
    }

    // ---- epilogue ----
    const int g = lane >> 2, tg = lane & 3;
    const int row0 = wm + g, row1 = row0 + 8;
#pragma unroll
    for (int nf = 0; nf < 8; nf++) {
        const int d = nf * 8 + tg * 2;
        float2 v0, v1;
        v0.x = o[nf][0] * inv0; v0.y = o[nf][1] * inv0;
        v1.x = o[nf][2] * inv1; v1.y = o[nf][3] * inv1;
        *(float2*)&go[base + (size_t)row0 * rstr + d] = v0;
        *(float2*)&go[base + (size_t)row1 * rstr + d] = v1;
    }
}

// ============================================================================
// kernel_launch
// ============================================================================
extern "C" void kernel_launch(void* const* d_in, const int* in_sizes, int n_in,
                              void* d_out, int out_size)
{
    const float* query = (const float*)d_in[0];
    const float* key   = (const float*)d_in[1];
    const float* value = (const float*)d_in[2];
    const float* Wq    = (const float*)d_in[3];
    const float* bq    = (const float*)d_in[4];
    const float* Wk    = (const float*)d_in[5];
    const float* bk    = (const float*)d_in[6];
    const float* Wv    = (const float*)d_in[7];
    const float* bv    = (const float*)d_in[8];
    const float* Wo    = (const float*)d_in[9];
    const float* bo    = (const float*)d_in[10];
    float* out = (float*)d_out;

    float *pq, *pk, *pv, *pa;
    uint16_t *wh;
    cudaGetSymbolAddress((void**)&pq, g_q);
    cudaGetSymbolAddress((void**)&pk, g_k);
    cudaGetSymbolAddress((void**)&pv, g_v);
    cudaGetSymbolAddress((void**)&pa, g_att);
    cudaGetSymbolAddress((void**)&wh, g_wh);

    const int gsmem = 2 * STG;   // 40960 B
    static int s_attr = 0;
    if (!s_attr) {
        cudaFuncSetAttribute(gemm_mma, cudaFuncAttributeMaxDynamicSharedMemorySize, gsmem);
        cudaFuncSetAttribute(attn_mma, cudaFuncAttributeMaxDynamicSharedMemorySize, ATT_SMEM);
        s_attr = 1;
    }

    const int n4w = DMODEL * DMODEL / 4;
    conv_h<<<1024, 256>>>((const float4*)Wq, (uint2*)(wh + 0 * DMODEL * DMODEL), n4w);
    conv_h<<<1024, 256>>>((const float4*)Wk, (uint2*)(wh + 1 * DMODEL * DMODEL), n4w);
    conv_h<<<1024, 256>>>((const float4*)Wv, (uint2*)(wh + 2 * DMODEL * DMODEL), n4w);
    conv_h<<<1024, 256>>>((const float4*)Wo, (uint2*)(wh + 3 * DMODEL * DMODEL), n4w);

    const dim3 ggrid(DMODEL / 128, MROWS / 128);   // (8, 256)
    gemm_mma<<<ggrid, 256, gsmem>>>(query, wh + 0 * DMODEL * DMODEL, bq, pq);
    gemm_mma<<<ggrid, 256, gsmem>>>(key,   wh + 1 * DMODEL * DMODEL, bk, pk);
    gemm_mma<<<ggrid, 256, gsmem>>>(value, wh + 2 * DMODEL * DMODEL, bv, pv);

    attn_mma<<<dim3(NN, NHEAD), 256, ATT_SMEM>>>(pq, pk, pv, pa);

    gemm_mma<<<ggrid, 256, gsmem>>>(pa, wh + 3 * DMODEL * DMODEL, bo, out);
}

// round 16
// speedup vs baseline: 1.5361x; 1.1695x over previous
#include <cuda_runtime.h>
#include <cuda_fp16.h>
#include <cstdint>
#include <cstddef>

#define DMODEL 1024
#define NHEAD  16
#define DK     64
#define BB     128
#define NN     256
#define MROWS  (BB * NN)   // 32768
#define DD     (DMODEL * DMODEL)

typedef unsigned long long ull;

// ============================ helpers ============================
__device__ __forceinline__ uint32_t smem_u32(const void* p) {
    uint32_t a;
    asm("{ .reg .u64 t; cvta.to.shared.u64 t, %1; cvt.u32.u64 %0, t; }" : "=r"(a) : "l"(p));
    return a;
}
__device__ __forceinline__ uint32_t pack2h(float x, float y) {  // low=x, high=y
    uint32_t r; asm("cvt.rn.f16x2.f32 %0, %2, %1;" : "=r"(r) : "f"(x), "f"(y)); return r;
}
__device__ __forceinline__ float fast_exp2(float x) {
    float y; asm("ex2.approx.f32 %0, %1;" : "=f"(y) : "f"(x)); return y;
}
__device__ __forceinline__ void mma16816(float* c, const uint32_t* a, const uint32_t* b) {
    asm volatile("mma.sync.aligned.m16n8k16.row.col.f32.f16.f16.f32 "
        "{%0,%1,%2,%3}, {%4,%5,%6,%7}, {%8,%9}, {%0,%1,%2,%3};"
        : "+f"(c[0]), "+f"(c[1]), "+f"(c[2]), "+f"(c[3])
        : "r"(a[0]), "r"(a[1]), "r"(a[2]), "r"(a[3]), "r"(b[0]), "r"(b[1]));
}
__device__ __forceinline__ void ldsm4(uint32_t* r, uint32_t a) {
    asm volatile("ldmatrix.sync.aligned.m8n8.x4.shared.b16 {%0,%1,%2,%3}, [%4];"
        : "=r"(r[0]), "=r"(r[1]), "=r"(r[2]), "=r"(r[3]) : "r"(a));
}
__device__ __forceinline__ void sts64(uint32_t a, uint32_t x, uint32_t y) {
    asm volatile("st.shared.v2.b32 [%0], {%1,%2};" :: "r"(a), "r"(x), "r"(y) : "memory");
}
__device__ __forceinline__ void sts16(uint32_t a, uint32_t v) {
    asm volatile("st.shared.b16 [%0], %1;" :: "r"(a), "r"(v) : "memory");
}
__device__ __forceinline__ void cpa16(uint32_t dst, const void* src) {
    asm volatile("cp.async.cg.shared.global [%0], [%1], 16;" :: "r"(dst), "l"(src));
}
#define CP_COMMIT() asm volatile("cp.async.commit_group;" ::: "memory")
#define CP_WAIT0()  asm volatile("cp.async.wait_group 0;" ::: "memory")

// ---- scratch ----
__device__ __align__(256) float    g_q[MROWS * DMODEL];
__device__ __align__(256) float    g_k[MROWS * DMODEL];
__device__ __align__(256) float    g_v[MROWS * DMODEL];
__device__ __align__(256) uint16_t g_qh[MROWS * DMODEL];
__device__ __align__(256) uint16_t g_kh[MROWS * DMODEL];
__device__ __align__(256) uint16_t g_vh[MROWS * DMODEL];
__device__ __align__(256) uint16_t g_ah[MROWS * DMODEL];
__device__ __align__(256) uint16_t g_wh[4][DD];

// ============================================================================
// prepass: f32 -> fp16 (hi only)
// ============================================================================
__global__ void conv_h(const float4* __restrict__ src, uint2* __restrict__ hi, int n4)
{
    for (int i = blockIdx.x * blockDim.x + threadIdx.x; i < n4;
         i += gridDim.x * blockDim.x) {
        const float4 v = src[i];
        hi[i] = make_uint2(pack2h(v.x, v.y), pack2h(v.z, v.w));
    }
}

// ============================================================================
// HMMA GEMM, pure cp.async: C = A(fp16) @ W^T(fp16) + bias.
// BM=BN=128, BK=32, 8 warps (warp tile 64x32), fp32 acc, pitch-80,
// double-buffered, 2 CTA/SM. gridDim.z selects among 3 (A, bias, C) sets
// (Q/K/V fused launch); W at Wbase + z*DD.
// ============================================================================
#define TP   80
#define TSZ  10240
#define STG  20480
#define NKS  32

__global__ void __launch_bounds__(256, 2) gemm_h(
    const uint16_t* __restrict__ A0, const uint16_t* __restrict__ A1,
    const uint16_t* __restrict__ A2, const uint16_t* __restrict__ Wbase,
    const float* __restrict__ b0, const float* __restrict__ b1,
    const float* __restrict__ b2,
    float* __restrict__ C0, float* __restrict__ C1, float* __restrict__ C2)
{
    extern __shared__ __align__(128) char dsm[];
    const uint32_t sb = smem_u32(dsm);
    const int t = threadIdx.x, lane = t & 31, wid = t >> 5;
    const int bm = blockIdx.y << 7, bn = blockIdx.x << 7;
    const int z = blockIdx.z;

    const uint16_t* A    = (z == 0) ? A0 : (z == 1) ? A1 : A2;
    const float*    bias = (z == 0) ? b0 : (z == 1) ? b1 : b2;
    float*          C    = (z == 0) ? C0 : (z == 1) ? C1 : C2;
    const uint16_t* Wh   = Wbase + (size_t)z * DD;

    const int lrow = t >> 1, lh = t & 1;
    const uint16_t* pA  = A  + (size_t)(bm + lrow) * DMODEL + lh * 16;
    const uint16_t* pWh = Wh + (size_t)(bn + lrow) * DMODEL + lh * 16;
    const uint32_t lst = sb + (uint32_t)lrow * TP + (uint32_t)lh * 32;

    const int wm = (wid >> 2) * 64, wn = (wid & 3) * 32;
    const int rA = (lane & 7) + ((lane >> 3) & 1) * 8, hA = (lane >> 4) & 1;
    const int rB = (lane & 7) + ((lane >> 4) & 1) * 8, hB = (lane >> 3) & 1;
    uint32_t rowA[4], rowB[2];
#pragma unroll
    for (int mf = 0; mf < 4; mf++) rowA[mf] = (uint32_t)((wm + mf * 16 + rA) * TP);
#pragma unroll
    for (int p = 0; p < 2; p++)    rowB[p] = (uint32_t)((wn + p * 16 + rB) * TP);

    float acc[4][4][4];
#pragma unroll
    for (int i = 0; i < 4; i++)
#pragma unroll
        for (int j = 0; j < 4; j++)
#pragma unroll
            for (int e = 0; e < 4; e++) acc[i][j][e] = 0.f;

    auto issue = [&](uint32_t d, int k0) {
        cpa16(d,            pA + k0);
        cpa16(d + 16,       pA + k0 + 8);
        cpa16(d + TSZ,      pWh + k0);
        cpa16(d + TSZ + 16, pWh + k0 + 8);
        CP_COMMIT();
    };

    issue(lst, 0);
    CP_WAIT0();
    __syncthreads();

    for (int s = 0; s < NKS; s++) {
        if (s + 1 < NKS)
            issue(lst + (uint32_t)((s + 1) & 1) * STG, (s + 1) * 32);

        const uint32_t base = sb + (uint32_t)(s & 1) * STG;
#pragma unroll
        for (int ks = 0; ks < 2; ks++) {
            const uint32_t offA = (uint32_t)(ks * 32 + hA * 16);
            const uint32_t offB = (uint32_t)(ks * 32 + hB * 16);
            uint32_t af[4][4], wf[2][4];
#pragma unroll
            for (int mf = 0; mf < 4; mf++) ldsm4(af[mf], base + rowA[mf] + offA);
#pragma unroll
            for (int p = 0; p < 2; p++)    ldsm4(wf[p], base + TSZ + rowB[p] + offB);
#pragma unroll
            for (int mf = 0; mf < 4; mf++)
#pragma unroll
                for (int nf = 0; nf < 4; nf++)
                    mma16816(acc[mf][nf], af[mf], &wf[nf >> 1][(nf & 1) * 2]);
        }

        CP_WAIT0();
        __syncthreads();
    }

    const int g = lane >> 2, tg = lane & 3;
#pragma unroll
    for (int mf = 0; mf < 4; mf++) {
        const int row0 = bm + wm + mf * 16 + g;
#pragma unroll
        for (int nf = 0; nf < 4; nf++) {
            const int col = bn + wn + nf * 8 + tg * 2;
            const float bx = bias[col], by = bias[col + 1];
            float2 o0, o1;
            o0.x = acc[mf][nf][0] + bx; o0.y = acc[mf][nf][1] + by;
            o1.x = acc[mf][nf][2] + bx; o1.y = acc[mf][nf][3] + by;
            *(float2*)&C[(size_t)row0 * DMODEL + col]       = o0;
            *(float2*)&C[(size_t)(row0 + 8) * DMODEL + col] = o1;
        }
    }
}

// ============================================================================
// HMMA intersample attention (math identical to R15): one block per (h, n).
// Output written as packed fp16 (consumed directly by the final GEMM —
// same quantization point the GEMM would apply, so bit-identical results).
// ============================================================================
#define PQ   72
#define PVT  136
#define OFF_QH 0
#define OFF_QL 18432
#define OFF_KH 36864
#define OFF_VH 55296
#define ATT_SMEM 72704

__global__ void __launch_bounds__(256, 2) attn_mma(
    const float* __restrict__ gq, const float* __restrict__ gk,
    const float* __restrict__ gv, uint16_t* __restrict__ oh)
{
    extern __shared__ __align__(128) uint16_t sm2[];
    const uint32_t sb = smem_u32(sm2);
    const int t = threadIdx.x, lane = t & 31, wid = t >> 5;
    const int n = blockIdx.x, h = blockIdx.y;
    const int    base = n * DMODEL + h * DK;
    const size_t rstr = (size_t)NN * DMODEL;

    {
        const int row = t >> 1, lh = t & 1;
        const float* qp = gq + base + (size_t)row * rstr + lh * 32;
        const float* kp = gk + base + (size_t)row * rstr + lh * 32;
        const float* vp = gv + base + (size_t)row * rstr + lh * 32;
        const uint32_t qdst = sb + (uint32_t)(row * PQ + lh * 32) * 2;
#pragma unroll
        for (int i = 0; i < 8; i++) {
            const float4 qv = *(const float4*)(qp + i * 4);
            const float4 kv = *(const float4*)(kp + i * 4);
            const float4 vv = *(const float4*)(vp + i * 4);
            uint32_t h0 = pack2h(qv.x, qv.y), h1 = pack2h(qv.z, qv.w);
            __half2 a0 = *(const __half2*)&h0, a1 = *(const __half2*)&h1;
            uint32_t l0 = pack2h(qv.x - __low2float(a0), qv.y - __high2float(a0));
            uint32_t l1 = pack2h(qv.z - __low2float(a1), qv.w - __high2float(a1));
            sts64(qdst + OFF_QH + i * 8, h0, h1);
            sts64(qdst + OFF_QL + i * 8, l0, l1);
            h0 = pack2h(kv.x, kv.y); h1 = pack2h(kv.z, kv.w);
            sts64(qdst + OFF_KH + i * 8, h0, h1);
            const float vs[4] = { vv.x, vv.y, vv.z, vv.w };
#pragma unroll
            for (int j = 0; j < 4; j++) {
                const int d = lh * 32 + i * 4 + j;
                const __half vh = __float2half_rn(vs[j]);
                const uint32_t ta = sb + (uint32_t)(d * PVT + row) * 2;
                sts16(ta + OFF_VH, (uint32_t)__half_as_ushort(vh));
            }
        }
    }
    __syncthreads();

    const int wm = wid * 16;
    const int rA = (lane & 7) + ((lane >> 3) & 1) * 8, hA = (lane >> 4) & 1;
    const int rB = (lane & 7) + ((lane >> 4) & 1) * 8, hB = (lane >> 3) & 1;
    const uint32_t rowAq = (uint32_t)((wm + rA) * PQ) * 2;

    float s[16][4];
#pragma unroll
    for (int i = 0; i < 16; i++)
#pragma unroll
        for (int e = 0; e < 4; e++) s[i][e] = 0.f;

#pragma unroll
    for (int ks = 0; ks < 4; ks++) {
        const uint32_t offA = (uint32_t)((ks * 2 + hA) * 16);
        const uint32_t offB = (uint32_t)((ks * 2 + hB) * 16);
        uint32_t aqh[4], aql[4], kf[8][4];
        ldsm4(aqh, sb + OFF_QH + rowAq + offA);
        ldsm4(aql, sb + OFF_QL + rowAq + offA);
#pragma unroll
        for (int p = 0; p < 8; p++)
            ldsm4(kf[p], sb + OFF_KH + (uint32_t)((p * 16 + rB) * PQ) * 2 + offB);
#pragma unroll
        for (int nf = 0; nf < 16; nf++) mma16816(s[nf], aqh, &kf[nf >> 1][(nf & 1) * 2]);
#pragma unroll
        for (int nf = 0; nf < 16; nf++) mma16816(s[nf], aql, &kf[nf >> 1][(nf & 1) * 2]);
    }

    float mx0 = -1e30f, mx1 = -1e30f;
#pragma unroll
    for (int nf = 0; nf < 16; nf++) {
        mx0 = fmaxf(mx0, fmaxf(s[nf][0], s[nf][1]));
        mx1 = fmaxf(mx1, fmaxf(s[nf][2], s[nf][3]));
    }
    mx0 = fmaxf(mx0, __shfl_xor_sync(0xffffffff, mx0, 1));
    mx0 = fmaxf(mx0, __shfl_xor_sync(0xffffffff, mx0, 2));
    mx1 = fmaxf(mx1, __shfl_xor_sync(0xffffffff, mx1, 1));
    mx1 = fmaxf(mx1, __shfl_xor_sync(0xffffffff, mx1, 2));
    const float cf = 0.125f * 1.4426950408889634f;
    float sum0 = 0.f, sum1 = 0.f;
#pragma unroll
    for (int nf = 0; nf < 16; nf++) {
        s[nf][0] = fast_exp2((s[nf][0] - mx0) * cf);
        s[nf][1] = fast_exp2((s[nf][1] - mx0) * cf);
        s[nf][2] = fast_exp2((s[nf][2] - mx1) * cf);
        s[nf][3] = fast_exp2((s[nf][3] - mx1) * cf);
        sum0 += s[nf][0] + s[nf][1];
        sum1 += s[nf][2] + s[nf][3];
    }
    sum0 += __shfl_xor_sync(0xffffffff, sum0, 1);
    sum0 += __shfl_xor_sync(0xffffffff, sum0, 2);
    sum1 += __shfl_xor_sync(0xffffffff, sum1, 1);
    sum1 += __shfl_xor_sync(0xffffffff, sum1, 2);
    const float inv0 = 1.0f / sum0, inv1 = 1.0f / sum1;

    float o[8][4];
#pragma unroll
    for (int i = 0; i < 8; i++)
#pragma unroll
        for (int e = 0; e < 4; e++) o[i][e] = 0.f;

#pragma unroll
    for (int ks = 0; ks < 8; ks++) {
        uint32_t ph[4], pl[4];
        {
            const float* e0 = s[2 * ks];
            const float* e1 = s[2 * ks + 1];
            ph[0] = pack2h(e0[0], e0[1]); ph[1] = pack2h(e0[2], e0[3]);
            ph[2] = pack2h(e1[0], e1[1]); ph[3] = pack2h(e1[2], e1[3]);
            const __half2 q0 = *(const __half2*)&ph[0], q1 = *(const __half2*)&ph[1];
            const __half2 q2 = *(const __half2*)&ph[2], q3 = *(const __half2*)&ph[3];
            pl[0] = pack2h(e0[0] - __low2float(q0), e0[1] - __high2float(q0));
            pl[1] = pack2h(e0[2] - __low2float(q1), e0[3] - __high2float(q1));
            pl[2] = pack2h(e1[0] - __low2float(q2), e1[1] - __high2float(q2));
            pl[3] = pack2h(e1[2] - __low2float(q3), e1[3] - __high2float(q3));
        }
        const uint32_t offB = (uint32_t)((ks * 2 + hB) * 16);
        uint32_t vf[4][4];
#pragma unroll
        for (int p = 0; p < 4; p++)
            ldsm4(vf[p], sb + OFF_VH + (uint32_t)((p * 16 + rB) * PVT) * 2 + offB);
#pragma unroll
        for (int nf = 0; nf < 8; nf++) mma16816(o[nf], ph, &vf[nf >> 1][(nf & 1) * 2]);
#pragma unroll
        for (int nf = 0; nf < 8; nf++) mma16816(o[nf], pl, &vf[nf >> 1][(nf & 1) * 2]);
    }

    // ---- epilogue: write fp16 (same quantization the GEMM would apply) ----
    const int g = lane >> 2, tg = lane & 3;
    const int row0 = wm + g, row1 = row0 + 8;
#pragma unroll
    for (int nf = 0; nf < 8; nf++) {
        const int d = nf * 8 + tg * 2;
        const uint32_t p0 = pack2h(o[nf][0] * inv0, o[nf][1] * inv0);
        const uint32_t p1 = pack2h(o[nf][2] * inv1, o[nf][3] * inv1);
        *(uint32_t*)&oh[base + (size_t)row0 * rstr + d] = p0;
        *(uint32_t*)&oh[base + (size_t)row1 * rstr + d] = p1;
    }
}

// ============================================================================
// kernel_launch
// ============================================================================
extern "C" void kernel_launch(void* const* d_in, const int* in_sizes, int n_in,
                              void* d_out, int out_size)
{
    const float* query = (const float*)d_in[0];
    const float* key   = (const float*)d_in[1];
    const float* value = (const float*)d_in[2];
    const float* Wq    = (const float*)d_in[3];
    const float* bq    = (const float*)d_in[4];
    const float* Wk    = (const float*)d_in[5];
    const float* bk    = (const float*)d_in[6];
    const float* Wv    = (const float*)d_in[7];
    const float* bv    = (const float*)d_in[8];
    const float* Wo    = (const float*)d_in[9];
    const float* bo    = (const float*)d_in[10];
    float* out = (float*)d_out;

    float *pq, *pk, *pv;
    uint16_t *qh, *kh, *vh, *ah, *wh;
    cudaGetSymbolAddress((void**)&pq, g_q);
    cudaGetSymbolAddress((void**)&pk, g_k);
    cudaGetSymbolAddress((void**)&pv, g_v);
    cudaGetSymbolAddress((void**)&qh, g_qh);
    cudaGetSymbolAddress((void**)&kh, g_kh);
    cudaGetSymbolAddress((void**)&vh, g_vh);
    cudaGetSymbolAddress((void**)&ah, g_ah);
    cudaGetSymbolAddress((void**)&wh, g_wh);

    const int gsmem = 2 * STG;   // 40960 B
    static int s_attr = 0;
    if (!s_attr) {
        cudaFuncSetAttribute(gemm_h, cudaFuncAttributeMaxDynamicSharedMemorySize, gsmem);
        cudaFuncSetAttribute(attn_mma, cudaFuncAttributeMaxDynamicSharedMemorySize, ATT_SMEM);
        s_attr = 1;
    }

    const int n4w = DD / 4;
    const int n4i = MROWS * DMODEL / 4;
    conv_h<<<1024, 256>>>((const float4*)Wq, (uint2*)(wh + 0 * DD), n4w);
    conv_h<<<1024, 256>>>((const float4*)Wk, (uint2*)(wh + 1 * DD), n4w);
    conv_h<<<1024, 256>>>((const float4*)Wv, (uint2*)(wh + 2 * DD), n4w);
    conv_h<<<1024, 256>>>((const float4*)Wo, (uint2*)(wh + 3 * DD), n4w);
    conv_h<<<4096, 256>>>((const float4*)query, (uint2*)qh, n4i);
    conv_h<<<4096, 256>>>((const float4*)key,   (uint2*)kh, n4i);
    conv_h<<<4096, 256>>>((const float4*)value, (uint2*)vh, n4i);

    // fused Q/K/V projection GEMMs
    gemm_h<<<dim3(DMODEL / 128, MROWS / 128, 3), 256, gsmem>>>(
        qh, kh, vh, wh, bq, bk, bv, pq, pk, pv);

    attn_mma<<<dim3(NN, NHEAD), 256, ATT_SMEM>>>(pq, pk, pv, ah);

    // output GEMM (z=0 path, W offset pre-applied)
    gemm_h<<<dim3(DMODEL / 128, MROWS / 128, 1), 256, gsmem>>>(
        ah, ah, ah, wh + 3 * DD, bo, bo, bo, out, out, out);
}